// round 17
// baseline (speedup 1.0000x reference)
#include <cuda_runtime.h>
#include <cuda_fp16.h>
#include <cstdint>

#define NROWS 131072
#define DIN   512
#define NH    512
#define DOUT  128
#define NBOUNDS 24

// ---------------- device scratch ---------------------------------------------
__device__ __align__(256) __half g_actA[(size_t)NROWS * 512];
__device__ __align__(256) __half g_actB[(size_t)NROWS * 512];
// weights transposed [N][K], single fp16 plane
__device__ __align__(256) __half g_wi[NH * DIN];
__device__ __align__(256) __half g_wh[NH * NH];
__device__ __align__(256) __half g_wo[DOUT * NH];
__device__ unsigned g_min_enc[DIN];
__device__ unsigned g_max_enc[DIN];

// ---------------- helpers ----------------------------------------------------
__device__ __forceinline__ uint32_t smem_u32(const void* p) {
    uint32_t a;
    asm("{ .reg .u64 t; cvta.to.shared.u64 t, %1; cvt.u32.u64 %0, t; }"
        : "=r"(a) : "l"(p));
    return a;
}
__device__ __forceinline__ void ldsm4(uint32_t* r, uint32_t a) {
    asm volatile("ldmatrix.sync.aligned.m8n8.x4.shared.b16 {%0,%1,%2,%3}, [%4];"
                 : "=r"(r[0]), "=r"(r[1]), "=r"(r[2]), "=r"(r[3]) : "r"(a));
}
__device__ __forceinline__ void mma16816h(float* d, const uint32_t* a,
                                          uint32_t b0, uint32_t b1) {
    asm volatile(
        "mma.sync.aligned.m16n8k16.row.col.f32.f16.f16.f32 "
        "{%0,%1,%2,%3}, {%4,%5,%6,%7}, {%8,%9}, {%0,%1,%2,%3};"
        : "+f"(d[0]), "+f"(d[1]), "+f"(d[2]), "+f"(d[3])
        : "r"(a[0]), "r"(a[1]), "r"(a[2]), "r"(a[3]), "r"(b0), "r"(b1));
}
#define CP_ASYNC16(dst, src) \
    asm volatile("cp.async.cg.shared.global [%0], [%1], 16;" :: "r"(dst), "l"(src))
#define CP_COMMIT() asm volatile("cp.async.commit_group;" ::: "memory")
#define CP_WAIT2()  asm volatile("cp.async.wait_group 2;" ::: "memory")

// ---------------- min/max + discretize ---------------------------------------
__device__ __forceinline__ unsigned enc_f(float f) {
    unsigned u = __float_as_uint(f);
    return (u & 0x80000000u) ? ~u : (u | 0x80000000u);
}
__device__ __forceinline__ float dec_f(unsigned e) {
    unsigned u = (e & 0x80000000u) ? (e & 0x7FFFFFFFu) : ~e;
    return __uint_as_float(u);
}
__global__ void init_minmax() {
    int i = threadIdx.x;
    g_min_enc[i] = 0xFFFFFFFFu;
    g_max_enc[i] = 0x00000000u;
}
__global__ void colminmax(const float* __restrict__ x) {
    const int col = threadIdx.x;
    const size_t base = (size_t)blockIdx.x * 512 * DIN + col;
    float v0 = x[base];
    float mn = v0, mx = v0;
    for (int r = 1; r < 512; r++) {
        float v = x[base + (size_t)r * DIN];
        mn = fminf(mn, v);
        mx = fmaxf(mx, v);
    }
    atomicMin(&g_min_enc[col], enc_f(mn));
    atomicMax(&g_max_enc[col], enc_f(mx));
}
// Windowed bucketize: candidate bin from scaled position, then 6 exact
// boundary compares (covers the <=1.5-bin error of the exact formula).
__global__ void discretize(const float* __restrict__ x) {
    __shared__ float sh_frac[NBOUNDS];
    const int col = threadIdx.x;
    if (col < NBOUNDS) sh_frac[col] = __fdiv_rn((float)(col + 1), 25.0f);
    __syncthreads();
    const float bmin = dec_f(g_min_enc[col]);
    const float bmax = dec_f(g_max_enc[col]);
    const float range = __fsub_rn(bmax, bmin);
    const float s = range > 0.0f ? __fdiv_rn(25.0f, range) : 0.0f;
    const size_t base = (size_t)blockIdx.x * 512 * DIN + col;
    for (int r = 0; r < 512; r++) {
        float v = x[base + (size_t)r * DIN];
        float t = (v - bmin) * s;
        int c = (int)t;
        int b0 = min(max(c - 3, 0), 18);
        int idx = b0;
#pragma unroll
        for (int j = 0; j < 6; j++) {
            float bk = __fadd_rn(bmin, __fmul_rn(range, sh_frac[b0 + j]));
            idx += (bk < v) ? 1 : 0;
        }
        g_actA[base + (size_t)r * DIN] = __float2half_rn((float)idx);
    }
}

// ---------------- weight convert + transpose (single fp16 plane) -------------
__global__ void wprep(const float* __restrict__ W, __half* __restrict__ hi,
                      int N, int K) {
    int i = blockIdx.x * blockDim.x + threadIdx.x;
    if (i >= N * K) return;
    int k = i / N, n = i % N;  // W is [K][N]
    hi[(size_t)n * K + k] = __float2half_rn(W[i]);  // transposed [N][K]
}

// ---------------- fp16 GEMM (mma.sync HMMA, fp32 accum) ----------------------
// C = relu(A@W + bias); A fp16 [M][512], W fp16 [N][512].
// BM=64, BN=NFRAG*64, 256 threads (2m x 4n warps, warp tile 32 x NFRAG*16).
// 2 buffers x BK=64, consumed in BK=32 halves -> 4 half-stage pipeline.
// Fragments for BOTH kk-slices of a half-chunk batched before the 32-mma run
// (halves exposed ldsm->mma dependency transitions).
#define SM_A  0
#define SM_B  8192

template <int NFRAG, int FINAL>
__global__ __launch_bounds__(256, 1)
void mlp_gemm(const __half* __restrict__ A, const __half* __restrict__ B,
              const float* __restrict__ bias,
              __half* __restrict__ Oh, float* __restrict__ Of32) {
    constexpr int BUFSZ = (1 + NFRAG) * 8192;
    extern __shared__ __align__(1024) unsigned char sm[];
    const uint32_t smb = smem_u32(sm);
    const int tid = threadIdx.x;
    const int lane = tid & 31, wid = tid >> 5;
    const int wm = wid >> 2, wn = wid & 3;      // 2 x 4 warp grid
    const int m0 = blockIdx.y * 64;
    const int n0 = blockIdx.x * (NFRAG * 64);

    float acc[2][2 * NFRAG][4];
#pragma unroll
    for (int i = 0; i < 2; i++)
#pragma unroll
        for (int j = 0; j < 2 * NFRAG; j++)
#pragma unroll
            for (int q = 0; q < 4; q++) acc[i][j][q] = 0.f;

    // ---- half-stage loader: BK=32 slab (64B per row) into half (ch&1) ------
    const int lr4 = tid >> 2, lc4 = tid & 3;
    auto load_half = [&](int ch) {
        const uint32_t sb = smb + (uint32_t)((ch >> 1) & 1) * BUFSZ;
        const int h4 = (ch & 1) * 4;
        const int k0 = ch * 32;
        {   // A plane: 64 rows x 4 slots (1 cp per thread)
            int r = lr4;
            uint32_t slot = (uint32_t)((h4 + lc4) ^ (r & 7)) << 4;
            CP_ASYNC16(sb + SM_A + r * 128 + slot,
                       A + (size_t)(m0 + r) * 512 + k0 + lc4 * 8);
        }
#pragma unroll
        for (int it = 0; it < NFRAG; it++) {    // B plane: NFRAG*64 rows
            int r = lr4 + it * 64;
            uint32_t slot = (uint32_t)((h4 + lc4) ^ (r & 7)) << 4;
            CP_ASYNC16(sb + SM_B + r * 128 + slot,
                       B + (size_t)(n0 + r) * 512 + k0 + lc4 * 8);
        }
    };

    const int arow = lane & 15;
    const int kbl  = lane >> 4;

    uint32_t aoff[2], boff[NFRAG];
    int amod[2], bmod[NFRAG];
#pragma unroll
    for (int mf = 0; mf < 2; mf++) {
        int r = wm * 32 + mf * 16 + arow;       // 0..63
        aoff[mf] = r * 128; amod[mf] = r & 7;
    }
#pragma unroll
    for (int g = 0; g < NFRAG; g++) {
        int r = wn * (NFRAG * 16) + g * 16 + arow;   // 0..NFRAG*64-1
        boff[g] = r * 128; bmod[g] = r & 7;
    }

    load_half(0); CP_COMMIT();
    load_half(1); CP_COMMIT();
    load_half(2); CP_COMMIT();

#pragma unroll 1
    for (int ch = 0; ch < 16; ch++) {
        CP_WAIT2();
        __syncthreads();
        if (ch + 3 < 16) load_half(ch + 3);
        CP_COMMIT();

        const uint32_t sb = smb + (uint32_t)((ch >> 1) & 1) * BUFSZ;
        const int h4 = (ch & 1) * 4;

        // batch ALL fragment loads for both kk-slices, then one 32-mma run
        uint32_t af[2][2][4], bf[2][NFRAG][4];
#pragma unroll
        for (int kk = 0; kk < 2; kk++) {
            const int c = h4 + kk * 2 + kbl;
#pragma unroll
            for (int mf = 0; mf < 2; mf++) {
                uint32_t o = aoff[mf] + (uint32_t)((c ^ amod[mf]) << 4);
                ldsm4(af[kk][mf], sb + SM_A + o);
            }
#pragma unroll
            for (int g = 0; g < NFRAG; g++) {
                uint32_t o = boff[g] + (uint32_t)((c ^ bmod[g]) << 4);
                ldsm4(bf[kk][g], sb + SM_B + o);
            }
        }
#pragma unroll
        for (int kk = 0; kk < 2; kk++)
#pragma unroll
            for (int g = 0; g < NFRAG; g++)
#pragma unroll
                for (int mf = 0; mf < 2; mf++) {
                    mma16816h(acc[mf][2 * g],     af[kk][mf], bf[kk][g][0], bf[kk][g][2]);
                    mma16816h(acc[mf][2 * g + 1], af[kk][mf], bf[kk][g][1], bf[kk][g][3]);
                }
    }

    // ---- epilogue: bias, relu, store ---------------------------------------
    const int OW = FINAL ? DOUT : 512;
    const int qr = lane >> 2, qc = lane & 3;
#pragma unroll
    for (int mf = 0; mf < 2; mf++) {
        const int r0 = m0 + wm * 32 + mf * 16 + qr;
#pragma unroll
        for (int nf = 0; nf < 2 * NFRAG; nf++) {
            const int n = n0 + wn * (NFRAG * 16) + nf * 8 + qc * 2;
            const float bv0 = bias[n], bv1 = bias[n + 1];
            const float* a = acc[mf][nf];
            float v00 = fmaxf(a[0] + bv0, 0.f);
            float v01 = fmaxf(a[1] + bv1, 0.f);
            float v10 = fmaxf(a[2] + bv0, 0.f);
            float v11 = fmaxf(a[3] + bv1, 0.f);
            if (FINAL) {
                *reinterpret_cast<float2*>(Of32 + (size_t)r0 * OW + n) =
                    make_float2(v00, v01);
                *reinterpret_cast<float2*>(Of32 + (size_t)(r0 + 8) * OW + n) =
                    make_float2(v10, v11);
            } else {
                __half h00 = __float2half_rn(v00), h01 = __float2half_rn(v01);
                __half h10 = __float2half_rn(v10), h11 = __float2half_rn(v11);
                uint32_t p0 = (uint32_t)*reinterpret_cast<unsigned short*>(&h00) |
                              ((uint32_t)*reinterpret_cast<unsigned short*>(&h01) << 16);
                uint32_t p1 = (uint32_t)*reinterpret_cast<unsigned short*>(&h10) |
                              ((uint32_t)*reinterpret_cast<unsigned short*>(&h11) << 16);
                *reinterpret_cast<uint32_t*>(Oh + (size_t)r0 * 512 + n) = p0;
                *reinterpret_cast<uint32_t*>(Oh + (size_t)(r0 + 8) * 512 + n) = p1;
            }
        }
    }
}

// ---------------- tail zero --------------------------------------------------
__global__ void zero_tail(float* out, size_t start, size_t count) {
    size_t i = (size_t)blockIdx.x * blockDim.x + threadIdx.x;
    if (i < count) out[start + i] = 0.0f;
}

// ---------------- launch -----------------------------------------------------
extern "C" void kernel_launch(void* const* d_in, const int* in_sizes, int n_in,
                              void* d_out, int out_size) {
    const float* x     = (const float*)d_in[0];
    const float* W_in  = (const float*)d_in[1];
    const float* b_in  = (const float*)d_in[2];
    const float* W_h   = (const float*)d_in[3];
    const float* b_h   = (const float*)d_in[4];
    const float* W_out = (const float*)d_in[5];
    const float* b_out = (const float*)d_in[6];
    float* out = (float*)d_out;

    __half *actA, *actB, *wi, *wh, *wo;
    cudaGetSymbolAddress((void**)&actA, g_actA);
    cudaGetSymbolAddress((void**)&actB, g_actB);
    cudaGetSymbolAddress((void**)&wi, g_wi);
    cudaGetSymbolAddress((void**)&wh, g_wh);
    cudaGetSymbolAddress((void**)&wo, g_wo);

    const size_t smemH = 2 * (1 + 4) * 8192;   // 80KB (hidden, NFRAG=4)
    const size_t smemF = 2 * (1 + 2) * 8192;   // 48KB (final, NFRAG=2)
    cudaFuncSetAttribute(mlp_gemm<4, 0>, cudaFuncAttributeMaxDynamicSharedMemorySize, smemH);
    cudaFuncSetAttribute(mlp_gemm<2, 1>, cudaFuncAttributeMaxDynamicSharedMemorySize, smemF);

    // prep (wprep first so ncu -s 5 lands on discretize)
    init_minmax<<<1, DIN>>>();
    wprep<<<(DIN * NH + 255) / 256, 256>>>(W_in, wi, NH, DIN);
    wprep<<<(NH * NH + 255) / 256, 256>>>(W_h, wh, NH, NH);
    wprep<<<(NH * DOUT + 255) / 256, 256>>>(W_out, wo, DOUT, NH);
    colminmax<<<NROWS / 512, DIN>>>(x);
    discretize<<<NROWS / 512, DIN>>>(x);     // -> actA (exact ints in fp16)

    dim3 blk(256);
    dim3 gh(2, NROWS / 64);    // hidden: N=512 -> 2 n-tiles of 256
    dim3 gf(1, NROWS / 64);    // final:  N=128 -> 1 n-tile of 128

    // L1 (exact input)
    mlp_gemm<4, 0><<<gh, blk, smemH>>>(actA, wi, b_in, actB, nullptr);
    // L2..L6: shared W_h, ping-pong
    mlp_gemm<4, 0><<<gh, blk, smemH>>>(actB, wh, b_h, actA, nullptr);
    mlp_gemm<4, 0><<<gh, blk, smemH>>>(actA, wh, b_h, actB, nullptr);
    mlp_gemm<4, 0><<<gh, blk, smemH>>>(actB, wh, b_h, actA, nullptr);
    mlp_gemm<4, 0><<<gh, blk, smemH>>>(actA, wh, b_h, actB, nullptr);
    mlp_gemm<4, 0><<<gh, blk, smemH>>>(actB, wh, b_h, actA, nullptr);
    // L7: final, fp32 out
    mlp_gemm<2, 1><<<gf, blk, smemF>>>(actA, wo, b_out, nullptr, out);

    size_t y_elems = (size_t)NROWS * DOUT;
    if ((size_t)out_size > y_elems) {
        size_t cnt = (size_t)out_size - y_elems;
        zero_tail<<<(unsigned)((cnt + 255) / 256), 256>>>(out, y_elems, cnt);
    }
}